// round 15
// baseline (speedup 1.0000x reference)
#include <cuda_runtime.h>
#include <cuda_bf16.h>

// MetaPolicyTransformer: N independent sequences, S=5, D=4, H=2 (hd=2), FF=16, L=3.
// One sequence per thread; f32x2 packed across the model dim; per-head QKV.
// R15 = R9 body + FF loop interchange (fp outer, s inner): FF weights load
// once per fp instead of once per (s,fp) -> 160 -> 32 LDS.128 per layer
// (~9% of all issue slots). Residual+bias folded into accumulator init.

#define D_ 4
#define S_ 5
#define FF_ 16
#define L_ 3
#define BLK 64

typedef unsigned long long u64;

__device__ __forceinline__ u64 pk2(float lo, float hi) {
    u64 r; asm("mov.b64 %0, {%1, %2};" : "=l"(r) : "f"(lo), "f"(hi)); return r;
}
__device__ __forceinline__ void upk2(u64 v, float& lo, float& hi) {
    asm("mov.b64 {%0, %1}, %2;" : "=f"(lo), "=f"(hi) : "l"(v));
}
__device__ __forceinline__ u64 fma2(u64 a, u64 b, u64 c) {
    u64 r; asm("fma.rn.f32x2 %0, %1, %2, %3;" : "=l"(r) : "l"(a), "l"(b), "l"(c)); return r;
}
__device__ __forceinline__ u64 add2(u64 a, u64 b) {
    u64 r; asm("add.rn.f32x2 %0, %1, %2;" : "=l"(r) : "l"(a), "l"(b)); return r;
}
__device__ __forceinline__ u64 mul2(u64 a, u64 b) {
    u64 r; asm("mul.rn.f32x2 %0, %1, %2;" : "=l"(r) : "l"(a), "l"(b)); return r;
}
__device__ __forceinline__ float ex2a(float x) {
    float r; asm("ex2.approx.f32 %0, %1;" : "=f"(r) : "f"(x)); return r;
}
__device__ __forceinline__ float rcpa(float x) {
    float r; asm("rcp.approx.f32 %0, %1;" : "=f"(r) : "f"(x)); return r;
}
__device__ __forceinline__ u64 relu2(u64 v) {
    float a, b; upk2(v, a, b);
    return pk2(fmaxf(a, 0.0f), fmaxf(b, 0.0f));
}

__global__ __launch_bounds__(BLK) void mpt_kernel(
    const float* __restrict__ xin,   // (N, 4, 4)
    const float* __restrict__ cls,   // (4,)
    const float* __restrict__ Wqkv,  // (3, 12, 4)
    const float* __restrict__ bqkv,  // (3, 12)
    const float* __restrict__ Wo,    // (3, 4, 4)
    const float* __restrict__ bo,    // (3, 4)
    const float* __restrict__ W1,    // (3, 16, 4)
    const float* __restrict__ b1,    // (3, 16)
    const float* __restrict__ W2,    // (3, 4, 16)
    const float* __restrict__ b2,    // (3, 4)
    float* __restrict__ out_fg,      // (N, 4)
    float* __restrict__ out_sub,     // (N, 16)
    int N)
{
    // Output-pair packed weights as ulonglong2 (LDS.128).
    __shared__ ulonglong2 sQKV2[L_ * 12];
    __shared__ ulonglong2 sBQ2[L_ * 3];
    __shared__ u64        sWO[L_ * 8];      // [dp*4+c] = {Wo[2dp][c], Wo[2dp+1][c]}
    __shared__ u64        sBO[L_ * 2];
    __shared__ ulonglong2 sW12[L_ * 16];
    __shared__ u64        sB1[L_ * 8];
    __shared__ ulonglong2 sW22[L_ * 16];    // [fp*2+fh] = { {W2[0][f],W2[1][f]}, {W2[2][f],W2[3][f]} }
    __shared__ u64        sB2[L_ * 2];
    __shared__ float      scls[4];

    const float SCL = 0.70710678118654752f * 1.4426950408889634f; // 1/sqrt2 * log2e

    const int t = threadIdx.x;
    for (int i = t; i < L_ * 12; i += BLK) {
        int l = i / 12, rem = i % 12, p = rem / 2, ch = rem % 2;
        const float* base = Wqkv + l * 48;
        float a0 = base[(2 * p)     * 4 + 2 * ch];
        float a1 = base[(2 * p + 1) * 4 + 2 * ch];
        float b0 = base[(2 * p)     * 4 + 2 * ch + 1];
        float b1v = base[(2 * p + 1) * 4 + 2 * ch + 1];
        if (p < 2) { a0 *= SCL; a1 *= SCL; b0 *= SCL; b1v *= SCL; }
        sQKV2[i] = make_ulonglong2(pk2(a0, a1), pk2(b0, b1v));
    }
    for (int i = t; i < L_ * 3; i += BLK) {
        int l = i / 3, pp = i % 3;
        const float* base = bqkv + l * 12;
        float s0 = (pp == 0) ? SCL : 1.0f;
        u64 lo = pk2(base[4 * pp]     * s0, base[4 * pp + 1] * s0);
        u64 hi = pk2(base[4 * pp + 2], base[4 * pp + 3]);
        sBQ2[i] = make_ulonglong2(lo, hi);
    }
    for (int i = t; i < L_ * 8; i += BLK) {
        int l = i / 8, rem = i % 8, dp = rem / 4, c = rem % 4;
        sWO[i] = pk2(Wo[l * 16 + (2 * dp) * 4 + c], Wo[l * 16 + (2 * dp + 1) * 4 + c]);
    }
    for (int i = t; i < L_ * 2; i += BLK) {
        int l = i / 2, dp = i % 2;
        sBO[i] = pk2(bo[l * 4 + 2 * dp], bo[l * 4 + 2 * dp + 1]);
        sB2[i] = pk2(b2[l * 4 + 2 * dp], b2[l * 4 + 2 * dp + 1]);
    }
    for (int i = t; i < L_ * 16; i += BLK) {
        int l = i / 16, rem = i % 16, fp = rem / 2, ch = rem % 2;
        const float* base = W1 + l * 64;
        sW12[i] = make_ulonglong2(
            pk2(base[(2 * fp) * 4 + 2 * ch],     base[(2 * fp + 1) * 4 + 2 * ch]),
            pk2(base[(2 * fp) * 4 + 2 * ch + 1], base[(2 * fp + 1) * 4 + 2 * ch + 1]));
    }
    for (int i = t; i < L_ * 8; i += BLK) {
        int l = i / 8, fp = i % 8;
        sB1[i] = pk2(b1[l * 16 + 2 * fp], b1[l * 16 + 2 * fp + 1]);
    }
    for (int i = t; i < L_ * 16; i += BLK) {
        int l = i / 16, rem = i % 16, fp = rem / 2, fh = rem % 2;
        int f = 2 * fp + fh;
        const float* base = W2 + l * 64;
        sW22[i] = make_ulonglong2(pk2(base[0 * 16 + f], base[1 * 16 + f]),
                                  pk2(base[2 * 16 + f], base[3 * 16 + f]));
    }
    if (t < 4) scls[t] = cls[t];
    __syncthreads();

    const int n = blockIdx.x * BLK + t;
    if (n >= N) return;

    const float pe[S_][D_] = {
        { 0.0f,                  1.0f,                  0.0f,                   1.0f                 },
        { 0.84147098480789651f,  0.54030230586813977f,  0.0099998333341666645f, 0.99995000041666528f },
        { 0.90929742682568170f, -0.41614683654714241f,  0.019998666693333084f,  0.99980000666657776f },
        { 0.14112000805986722f, -0.98999249660044542f,  0.029995500337493652f,  0.99955003374899023f },
        { -0.75680249530792820f,-0.65364362086361194f,  0.039989334186634161f,  0.99920010665856564f }
    };

    float x[S_][D_];
    #pragma unroll
    for (int d = 0; d < D_; d++) x[0][d] = scls[d] + pe[0][d];
    const float4* xp = reinterpret_cast<const float4*>(xin + (size_t)n * 16);
    #pragma unroll
    for (int s = 1; s < S_; s++) {
        float4 r = xp[s - 1];
        x[s][0] = r.x + pe[s][0];
        x[s][1] = r.y + pe[s][1];
        x[s][2] = r.z + pe[s][2];
        x[s][3] = r.w + pe[s][3];
    }

    #pragma unroll 1
    for (int l = 0; l < L_; l++) {
        const ulonglong2* wq2 = sQKV2 + l * 12;
        const ulonglong2* bq2 = sBQ2  + l * 3;
        const u64*        wop = sWO   + l * 8;
        const u64*        bop = sBO   + l * 2;
        const ulonglong2* w1v = sW12  + l * 16;
        const u64*        b1p = sB1   + l * 8;
        const ulonglong2* w2v = sW22  + l * 16;
        const u64*        b2p = sB2   + l * 2;

        // residual accumulator (packed pairs), out-proj bias folded in
        u64 nxp[S_][2];
        #pragma unroll
        for (int s = 0; s < S_; s++) {
            nxp[s][0] = add2(pk2(x[s][0], x[s][1]), bop[0]);
            nxp[s][1] = add2(pk2(x[s][2], x[s][3]), bop[1]);
        }

        // attention, one head at a time; q/k/v computed per head
        #pragma unroll 1
        for (int h = 0; h < 2; h++) {
            const u64 bq_q = (h == 0) ? bq2[0].x : bq2[0].y;
            const u64 bq_k = (h == 0) ? bq2[1].x : bq2[1].y;
            const u64 bq_v = (h == 0) ? bq2[2].x : bq2[2].y;
            const u64 wo00 = wop[0 * 4 + 2 * h], wo01 = wop[0 * 4 + 2 * h + 1];
            const u64 wo10 = wop[1 * 4 + 2 * h], wo11 = wop[1 * 4 + 2 * h + 1];

            u64 qh[S_], vh[S_];
            float k0[S_], k1[S_];
            #pragma unroll
            for (int s = 0; s < S_; s++) {
                u64 xd0 = pk2(x[s][0], x[s][0]);
                u64 xd1 = pk2(x[s][1], x[s][1]);
                u64 xd2 = pk2(x[s][2], x[s][2]);
                u64 xd3 = pk2(x[s][3], x[s][3]);
                {
                    ulonglong2 wA = wq2[h * 2], wB = wq2[h * 2 + 1];
                    u64 a = bq_q;
                    a = fma2(xd0, wA.x, a);
                    a = fma2(xd1, wA.y, a);
                    a = fma2(xd2, wB.x, a);
                    a = fma2(xd3, wB.y, a);
                    qh[s] = a;
                }
                {
                    ulonglong2 wA = wq2[(2 + h) * 2], wB = wq2[(2 + h) * 2 + 1];
                    u64 a = bq_k;
                    a = fma2(xd0, wA.x, a);
                    a = fma2(xd1, wA.y, a);
                    a = fma2(xd2, wB.x, a);
                    a = fma2(xd3, wB.y, a);
                    upk2(a, k0[s], k1[s]);
                }
                {
                    ulonglong2 wA = wq2[(4 + h) * 2], wB = wq2[(4 + h) * 2 + 1];
                    u64 a = bq_v;
                    a = fma2(xd0, wA.x, a);
                    a = fma2(xd1, wA.y, a);
                    a = fma2(xd2, wB.x, a);
                    a = fma2(xd3, wB.y, a);
                    vh[s] = a;
                }
            }

            const u64 kt0a = pk2(k0[0], k0[1]), kt0b = pk2(k0[2], k0[3]);
            const u64 kt1a = pk2(k1[0], k1[1]), kt1b = pk2(k1[2], k1[3]);

            #pragma unroll
            for (int i = 0; i < S_; i++) {
                float q0, q1; upk2(qh[i], q0, q1);
                const u64 qb0 = pk2(q0, q0), qb1 = pk2(q1, q1);
                u64 sc01 = fma2(qb1, kt1a, mul2(qb0, kt0a));
                u64 sc23 = fma2(qb1, kt1b, mul2(qb0, kt0b));
                float s0, s1, s2, s3;
                upk2(sc01, s0, s1); upk2(sc23, s2, s3);
                float s4 = fmaf(q1, k1[4], q0 * k0[4]);
                float e0 = ex2a(s0), e1 = ex2a(s1), e2 = ex2a(s2),
                      e3 = ex2a(s3), e4 = ex2a(s4);
                float inv = rcpa(((e0 + e1) + (e2 + e3)) + e4);
                u64 o = mul2(pk2(e0, e0), vh[0]);
                o = fma2(pk2(e1, e1), vh[1], o);
                o = fma2(pk2(e2, e2), vh[2], o);
                o = fma2(pk2(e3, e3), vh[3], o);
                o = fma2(pk2(e4, e4), vh[4], o);
                o = mul2(o, pk2(inv, inv));
                float a0, a1; upk2(o, a0, a1);
                const u64 d0 = pk2(a0, a0), d1 = pk2(a1, a1);
                nxp[i][0] = fma2(d0, wo00, nxp[i][0]);
                nxp[i][0] = fma2(d1, wo01, nxp[i][0]);
                nxp[i][1] = fma2(d0, wo10, nxp[i][1]);
                nxp[i][1] = fma2(d1, wo11, nxp[i][1]);
            }
        }

        // FF, loops interchanged: fp OUTER (weights load once per fp), s inner.
        // xd dups hoisted from nxp; acc init folds residual + b2.
        {
            u64 xd[S_][D_];
            u64 acc[S_][2];
            #pragma unroll
            for (int s = 0; s < S_; s++) {
                float x0, x1, x2, x3;
                upk2(nxp[s][0], x0, x1);
                upk2(nxp[s][1], x2, x3);
                xd[s][0] = pk2(x0, x0);
                xd[s][1] = pk2(x1, x1);
                xd[s][2] = pk2(x2, x2);
                xd[s][3] = pk2(x3, x3);
                acc[s][0] = add2(nxp[s][0], b2p[0]);
                acc[s][1] = add2(nxp[s][1], b2p[1]);
            }
            #pragma unroll
            for (int fp = 0; fp < 8; fp++) {
                const ulonglong2 wA  = w1v[fp * 2];
                const ulonglong2 wB  = w1v[fp * 2 + 1];
                const u64        bb  = b1p[fp];
                const ulonglong2 w2a = w2v[fp * 2];
                const ulonglong2 w2b = w2v[fp * 2 + 1];
                #pragma unroll
                for (int s = 0; s < S_; s++) {
                    u64 a = bb;
                    a = fma2(xd[s][0], wA.x, a);
                    a = fma2(xd[s][1], wA.y, a);
                    a = fma2(xd[s][2], wB.x, a);
                    a = fma2(xd[s][3], wB.y, a);
                    u64 h1 = relu2(a);
                    float ha, hb; upk2(h1, ha, hb);
                    const u64 hba = pk2(ha, ha), hbb = pk2(hb, hb);
                    acc[s][0] = fma2(hba, w2a.x, acc[s][0]);
                    acc[s][1] = fma2(hba, w2a.y, acc[s][1]);
                    acc[s][0] = fma2(hbb, w2b.x, acc[s][0]);
                    acc[s][1] = fma2(hbb, w2b.y, acc[s][1]);
                }
            }
            #pragma unroll
            for (int s = 0; s < S_; s++) {
                upk2(acc[s][0], x[s][0], x[s][1]);
                upk2(acc[s][1], x[s][2], x[s][3]);
            }
        }
    }

    // outputs
    reinterpret_cast<float4*>(out_fg + (size_t)n * 4)[0] =
        make_float4(x[0][0], x[0][1], x[0][2], x[0][3]);
    float4* sub = reinterpret_cast<float4*>(out_sub + (size_t)n * 16);
    #pragma unroll
    for (int s = 1; s < S_; s++)
        sub[s - 1] = make_float4(x[s][0], x[s][1], x[s][2], x[s][3]);
}

extern "C" void kernel_launch(void* const* d_in, const int* in_sizes, int n_in,
                              void* d_out, int out_size) {
    const float* xin  = (const float*)d_in[0];
    const float* cls  = (const float*)d_in[1];
    const float* Wqkv = (const float*)d_in[2];
    const float* bqkv = (const float*)d_in[3];
    const float* Wo   = (const float*)d_in[4];
    const float* bo   = (const float*)d_in[5];
    const float* W1   = (const float*)d_in[6];
    const float* b1   = (const float*)d_in[7];
    const float* W2   = (const float*)d_in[8];
    const float* b2   = (const float*)d_in[9];

    const int N = in_sizes[0] / 16;
    float* out_fg  = (float*)d_out;
    float* out_sub = (float*)d_out + (size_t)N * 4;

    const int grid = (N + BLK - 1) / BLK;
    mpt_kernel<<<grid, BLK>>>(xin, cls, Wqkv, bqkv, Wo, bo, W1, b1, W2, b2,
                              out_fg, out_sub, N);
}

// round 16
// speedup vs baseline: 1.0390x; 1.0390x over previous
#include <cuda_runtime.h>
#include <cuda_bf16.h>

// MetaPolicyTransformer: N independent sequences, S=5, D=4, H=2 (hd=2), FF=16, L=3.
// One sequence per thread; f32x2 packed across the model dim; per-head QKV.
// FINAL (== R9, measured 195.3us): the plateau of this design family.
// R10-R15 established: forced reg caps spill (L2 traffic > occupancy gain),
// repacking layouts bloat ALU movs, LDS-width/interchange tweaks are neutral.
// fma-pipe op count is at the MAC floor (~620 packed ops/layer vs 620 minimal).

#define D_ 4
#define S_ 5
#define FF_ 16
#define L_ 3
#define BLK 64

typedef unsigned long long u64;

__device__ __forceinline__ u64 pk2(float lo, float hi) {
    u64 r; asm("mov.b64 %0, {%1, %2};" : "=l"(r) : "f"(lo), "f"(hi)); return r;
}
__device__ __forceinline__ void upk2(u64 v, float& lo, float& hi) {
    asm("mov.b64 {%0, %1}, %2;" : "=f"(lo), "=f"(hi) : "l"(v));
}
__device__ __forceinline__ u64 fma2(u64 a, u64 b, u64 c) {
    u64 r; asm("fma.rn.f32x2 %0, %1, %2, %3;" : "=l"(r) : "l"(a), "l"(b), "l"(c)); return r;
}
__device__ __forceinline__ u64 add2(u64 a, u64 b) {
    u64 r; asm("add.rn.f32x2 %0, %1, %2;" : "=l"(r) : "l"(a), "l"(b)); return r;
}
__device__ __forceinline__ u64 mul2(u64 a, u64 b) {
    u64 r; asm("mul.rn.f32x2 %0, %1, %2;" : "=l"(r) : "l"(a), "l"(b)); return r;
}
__device__ __forceinline__ float ex2a(float x) {
    float r; asm("ex2.approx.f32 %0, %1;" : "=f"(r) : "f"(x)); return r;
}
__device__ __forceinline__ float rcpa(float x) {
    float r; asm("rcp.approx.f32 %0, %1;" : "=f"(r) : "f"(x)); return r;
}
__device__ __forceinline__ u64 relu2(u64 v) {
    float a, b; upk2(v, a, b);
    return pk2(fmaxf(a, 0.0f), fmaxf(b, 0.0f));
}

__global__ __launch_bounds__(BLK) void mpt_kernel(
    const float* __restrict__ xin,   // (N, 4, 4)
    const float* __restrict__ cls,   // (4,)
    const float* __restrict__ Wqkv,  // (3, 12, 4)
    const float* __restrict__ bqkv,  // (3, 12)
    const float* __restrict__ Wo,    // (3, 4, 4)
    const float* __restrict__ bo,    // (3, 4)
    const float* __restrict__ W1,    // (3, 16, 4)
    const float* __restrict__ b1,    // (3, 16)
    const float* __restrict__ W2,    // (3, 4, 16)
    const float* __restrict__ b2,    // (3, 4)
    float* __restrict__ out_fg,      // (N, 4)
    float* __restrict__ out_sub,     // (N, 16)
    int N)
{
    // Output-pair packed weights as ulonglong2 (LDS.128).
    __shared__ ulonglong2 sQKV2[L_ * 12];
    __shared__ ulonglong2 sBQ2[L_ * 3];
    __shared__ u64        sWO[L_ * 8];      // [dp*4+c] = {Wo[2dp][c], Wo[2dp+1][c]}
    __shared__ u64        sBO[L_ * 2];
    __shared__ ulonglong2 sW12[L_ * 16];
    __shared__ u64        sB1[L_ * 8];
    __shared__ ulonglong2 sW22[L_ * 16];    // [fp*2+fh] = { {W2[0][f],W2[1][f]}, {W2[2][f],W2[3][f]} }
    __shared__ u64        sB2[L_ * 2];
    __shared__ float      scls[4];

    const float SCL = 0.70710678118654752f * 1.4426950408889634f; // 1/sqrt2 * log2e

    const int t = threadIdx.x;
    for (int i = t; i < L_ * 12; i += BLK) {
        int l = i / 12, rem = i % 12, p = rem / 2, ch = rem % 2;
        const float* base = Wqkv + l * 48;
        float a0 = base[(2 * p)     * 4 + 2 * ch];
        float a1 = base[(2 * p + 1) * 4 + 2 * ch];
        float b0 = base[(2 * p)     * 4 + 2 * ch + 1];
        float b1v = base[(2 * p + 1) * 4 + 2 * ch + 1];
        if (p < 2) { a0 *= SCL; a1 *= SCL; b0 *= SCL; b1v *= SCL; }
        sQKV2[i] = make_ulonglong2(pk2(a0, a1), pk2(b0, b1v));
    }
    for (int i = t; i < L_ * 3; i += BLK) {
        int l = i / 3, pp = i % 3;
        const float* base = bqkv + l * 12;
        float s0 = (pp == 0) ? SCL : 1.0f;
        u64 lo = pk2(base[4 * pp]     * s0, base[4 * pp + 1] * s0);
        u64 hi = pk2(base[4 * pp + 2], base[4 * pp + 3]);
        sBQ2[i] = make_ulonglong2(lo, hi);
    }
    for (int i = t; i < L_ * 8; i += BLK) {
        int l = i / 8, rem = i % 8, dp = rem / 4, c = rem % 4;
        sWO[i] = pk2(Wo[l * 16 + (2 * dp) * 4 + c], Wo[l * 16 + (2 * dp + 1) * 4 + c]);
    }
    for (int i = t; i < L_ * 2; i += BLK) {
        int l = i / 2, dp = i % 2;
        sBO[i] = pk2(bo[l * 4 + 2 * dp], bo[l * 4 + 2 * dp + 1]);
        sB2[i] = pk2(b2[l * 4 + 2 * dp], b2[l * 4 + 2 * dp + 1]);
    }
    for (int i = t; i < L_ * 16; i += BLK) {
        int l = i / 16, rem = i % 16, fp = rem / 2, ch = rem % 2;
        const float* base = W1 + l * 64;
        sW12[i] = make_ulonglong2(
            pk2(base[(2 * fp) * 4 + 2 * ch],     base[(2 * fp + 1) * 4 + 2 * ch]),
            pk2(base[(2 * fp) * 4 + 2 * ch + 1], base[(2 * fp + 1) * 4 + 2 * ch + 1]));
    }
    for (int i = t; i < L_ * 8; i += BLK) {
        int l = i / 8, fp = i % 8;
        sB1[i] = pk2(b1[l * 16 + 2 * fp], b1[l * 16 + 2 * fp + 1]);
    }
    for (int i = t; i < L_ * 16; i += BLK) {
        int l = i / 16, rem = i % 16, fp = rem / 2, fh = rem % 2;
        int f = 2 * fp + fh;
        const float* base = W2 + l * 64;
        sW22[i] = make_ulonglong2(pk2(base[0 * 16 + f], base[1 * 16 + f]),
                                  pk2(base[2 * 16 + f], base[3 * 16 + f]));
    }
    if (t < 4) scls[t] = cls[t];
    __syncthreads();

    const int n = blockIdx.x * BLK + t;
    if (n >= N) return;

    const float pe[S_][D_] = {
        { 0.0f,                  1.0f,                  0.0f,                   1.0f                 },
        { 0.84147098480789651f,  0.54030230586813977f,  0.0099998333341666645f, 0.99995000041666528f },
        { 0.90929742682568170f, -0.41614683654714241f,  0.019998666693333084f,  0.99980000666657776f },
        { 0.14112000805986722f, -0.98999249660044542f,  0.029995500337493652f,  0.99955003374899023f },
        { -0.75680249530792820f,-0.65364362086361194f,  0.039989334186634161f,  0.99920010665856564f }
    };

    float x[S_][D_];
    #pragma unroll
    for (int d = 0; d < D_; d++) x[0][d] = scls[d] + pe[0][d];
    const float4* xp = reinterpret_cast<const float4*>(xin + (size_t)n * 16);
    #pragma unroll
    for (int s = 1; s < S_; s++) {
        float4 r = xp[s - 1];
        x[s][0] = r.x + pe[s][0];
        x[s][1] = r.y + pe[s][1];
        x[s][2] = r.z + pe[s][2];
        x[s][3] = r.w + pe[s][3];
    }

    #pragma unroll 1
    for (int l = 0; l < L_; l++) {
        const ulonglong2* wq2 = sQKV2 + l * 12;
        const ulonglong2* bq2 = sBQ2  + l * 3;
        const u64*        wop = sWO   + l * 8;
        const u64*        bop = sBO   + l * 2;
        const ulonglong2* w1v = sW12  + l * 16;
        const u64*        b1p = sB1   + l * 8;
        const ulonglong2* w2v = sW22  + l * 16;
        const u64*        b2p = sB2   + l * 2;

        // residual accumulator (packed pairs), out-proj bias folded in
        u64 nxp[S_][2];
        #pragma unroll
        for (int s = 0; s < S_; s++) {
            nxp[s][0] = add2(pk2(x[s][0], x[s][1]), bop[0]);
            nxp[s][1] = add2(pk2(x[s][2], x[s][3]), bop[1]);
        }

        // attention, one head at a time; q/k/v computed per head
        #pragma unroll 1
        for (int h = 0; h < 2; h++) {
            const u64 bq_q = (h == 0) ? bq2[0].x : bq2[0].y;
            const u64 bq_k = (h == 0) ? bq2[1].x : bq2[1].y;
            const u64 bq_v = (h == 0) ? bq2[2].x : bq2[2].y;
            const u64 wo00 = wop[0 * 4 + 2 * h], wo01 = wop[0 * 4 + 2 * h + 1];
            const u64 wo10 = wop[1 * 4 + 2 * h], wo11 = wop[1 * 4 + 2 * h + 1];

            u64 qh[S_], vh[S_];
            float k0[S_], k1[S_];
            #pragma unroll
            for (int s = 0; s < S_; s++) {
                u64 xd0 = pk2(x[s][0], x[s][0]);
                u64 xd1 = pk2(x[s][1], x[s][1]);
                u64 xd2 = pk2(x[s][2], x[s][2]);
                u64 xd3 = pk2(x[s][3], x[s][3]);
                {
                    ulonglong2 wA = wq2[h * 2], wB = wq2[h * 2 + 1];
                    u64 a = bq_q;
                    a = fma2(xd0, wA.x, a);
                    a = fma2(xd1, wA.y, a);
                    a = fma2(xd2, wB.x, a);
                    a = fma2(xd3, wB.y, a);
                    qh[s] = a;
                }
                {
                    ulonglong2 wA = wq2[(2 + h) * 2], wB = wq2[(2 + h) * 2 + 1];
                    u64 a = bq_k;
                    a = fma2(xd0, wA.x, a);
                    a = fma2(xd1, wA.y, a);
                    a = fma2(xd2, wB.x, a);
                    a = fma2(xd3, wB.y, a);
                    upk2(a, k0[s], k1[s]);
                }
                {
                    ulonglong2 wA = wq2[(4 + h) * 2], wB = wq2[(4 + h) * 2 + 1];
                    u64 a = bq_v;
                    a = fma2(xd0, wA.x, a);
                    a = fma2(xd1, wA.y, a);
                    a = fma2(xd2, wB.x, a);
                    a = fma2(xd3, wB.y, a);
                    vh[s] = a;
                }
            }

            const u64 kt0a = pk2(k0[0], k0[1]), kt0b = pk2(k0[2], k0[3]);
            const u64 kt1a = pk2(k1[0], k1[1]), kt1b = pk2(k1[2], k1[3]);

            #pragma unroll
            for (int i = 0; i < S_; i++) {
                float q0, q1; upk2(qh[i], q0, q1);
                const u64 qb0 = pk2(q0, q0), qb1 = pk2(q1, q1);
                u64 sc01 = fma2(qb1, kt1a, mul2(qb0, kt0a));
                u64 sc23 = fma2(qb1, kt1b, mul2(qb0, kt0b));
                float s0, s1, s2, s3;
                upk2(sc01, s0, s1); upk2(sc23, s2, s3);
                float s4 = fmaf(q1, k1[4], q0 * k0[4]);
                float e0 = ex2a(s0), e1 = ex2a(s1), e2 = ex2a(s2),
                      e3 = ex2a(s3), e4 = ex2a(s4);
                u64 psum = add2(pk2(e0, e1), pk2(e2, e3));
                float pa, pb; upk2(psum, pa, pb);
                float inv = rcpa((pa + pb) + e4);
                u64 o = mul2(pk2(e0, e0), vh[0]);
                o = fma2(pk2(e1, e1), vh[1], o);
                o = fma2(pk2(e2, e2), vh[2], o);
                o = fma2(pk2(e3, e3), vh[3], o);
                o = fma2(pk2(e4, e4), vh[4], o);
                o = mul2(o, pk2(inv, inv));
                float a0, a1; upk2(o, a0, a1);
                const u64 d0 = pk2(a0, a0), d1 = pk2(a1, a1);
                nxp[i][0] = fma2(d0, wo00, nxp[i][0]);
                nxp[i][0] = fma2(d1, wo01, nxp[i][0]);
                nxp[i][1] = fma2(d0, wo10, nxp[i][1]);
                nxp[i][1] = fma2(d1, wo11, nxp[i][1]);
            }
        }

        #pragma unroll
        for (int s = 0; s < S_; s++) {
            upk2(nxp[s][0], x[s][0], x[s][1]);
            upk2(nxp[s][1], x[s][2], x[s][3]);
        }

        // FF + residual — biases from smem at point of use
        #pragma unroll
        for (int s = 0; s < S_; s++) {
            u64 xd0 = pk2(x[s][0], x[s][0]);
            u64 xd1 = pk2(x[s][1], x[s][1]);
            u64 xd2 = pk2(x[s][2], x[s][2]);
            u64 xd3 = pk2(x[s][3], x[s][3]);
            u64 acc0 = b2p[0], acc1 = b2p[1];
            #pragma unroll
            for (int fp = 0; fp < 8; fp++) {
                ulonglong2 wA = w1v[fp * 2];
                ulonglong2 wB = w1v[fp * 2 + 1];
                u64 a = b1p[fp];
                a = fma2(xd0, wA.x, a);
                a = fma2(xd1, wA.y, a);
                a = fma2(xd2, wB.x, a);
                a = fma2(xd3, wB.y, a);
                u64 h1 = relu2(a);
                float ha, hb; upk2(h1, ha, hb);
                const u64 hba = pk2(ha, ha), hbb = pk2(hb, hb);
                ulonglong2 w2a = w2v[fp * 2];
                ulonglong2 w2b = w2v[fp * 2 + 1];
                acc0 = fma2(hba, w2a.x, acc0);
                acc1 = fma2(hba, w2a.y, acc1);
                acc0 = fma2(hbb, w2b.x, acc0);
                acc1 = fma2(hbb, w2b.y, acc1);
            }
            u64 y0 = add2(acc0, pk2(x[s][0], x[s][1]));
            u64 y1 = add2(acc1, pk2(x[s][2], x[s][3]));
            upk2(y0, x[s][0], x[s][1]);
            upk2(y1, x[s][2], x[s][3]);
        }
    }

    // outputs
    reinterpret_cast<float4*>(out_fg + (size_t)n * 4)[0] =
        make_float4(x[0][0], x[0][1], x[0][2], x[0][3]);
    float4* sub = reinterpret_cast<float4*>(out_sub + (size_t)n * 16);
    #pragma unroll
    for (int s = 1; s < S_; s++)
        sub[s - 1] = make_float4(x[s][0], x[s][1], x[s][2], x[s][3]);
}

extern "C" void kernel_launch(void* const* d_in, const int* in_sizes, int n_in,
                              void* d_out, int out_size) {
    const float* xin  = (const float*)d_in[0];
    const float* cls  = (const float*)d_in[1];
    const float* Wqkv = (const float*)d_in[2];
    const float* bqkv = (const float*)d_in[3];
    const float* Wo   = (const float*)d_in[4];
    const float* bo   = (const float*)d_in[5];
    const float* W1   = (const float*)d_in[6];
    const float* b1   = (const float*)d_in[7];
    const float* W2   = (const float*)d_in[8];
    const float* b2   = (const float*)d_in[9];

    const int N = in_sizes[0] / 16;
    float* out_fg  = (float*)d_out;
    float* out_sub = (float*)d_out + (size_t)N * 4;

    const int grid = (N + BLK - 1) / BLK;
    mpt_kernel<<<grid, BLK>>>(xin, cls, Wqkv, bqkv, Wo, bo, W1, b1, W2, b2,
                              out_fg, out_sub, N);
}